// round 5
// baseline (speedup 1.0000x reference)
#include <cuda_runtime.h>
#include <cuda_bf16.h>
#include <cstdint>
#include <math.h>

#define BB   16
#define CIN  128
#define COUT 256
#define KK   9
#define HH   56
#define WW   56
#define HW   3136
#define KDIM (CIN*KK)   // 1152
#define HP   58         // padded H/W

// GEMM tiling (mma.sync bf16 path)
#define BM 64
#define BN 112          // 3136 = 28 * 112 ; covers exactly 2 image rows
#define BK 64           // bf16 K per mainloop chunk
#define NCHUNK (KDIM/BK) // 18

// ---------------- device scratch (no allocations allowed) ----------------
__device__ float g_ctx[BB*CIN];
__device__ float g_attn_sp[BB*KK];
__device__ float g_attn_in[BB*CIN];
__device__ float g_attn_out[BB*COUT];
__device__ __align__(16) __nv_bfloat16 g_dynA_hi[(size_t)BB*COUT*KDIM]; // 9.4MB
__device__ __align__(16) __nv_bfloat16 g_dynA_lo[(size_t)BB*COUT*KDIM]; // 9.4MB
__device__ __align__(16) uint32_t g_xpad[(size_t)BB*CIN*HP*HP];         // 27.5MB (hi|lo<<16)

// ======================= helpers =====================
__device__ __forceinline__ uint32_t smem_u32(const void* p) {
    uint32_t a;
    asm("{ .reg .u64 t; cvta.to.shared.u64 t, %1; cvt.u32.u64 %0, t; }"
        : "=r"(a) : "l"(p));
    return a;
}
__device__ __forceinline__ void ldm_x4(uint32_t* r, uint32_t addr) {
    asm volatile("ldmatrix.sync.aligned.m8n8.x4.shared.b16 {%0,%1,%2,%3}, [%4];"
        : "=r"(r[0]), "=r"(r[1]), "=r"(r[2]), "=r"(r[3]) : "r"(addr));
}
__device__ __forceinline__ void ldm_x2(uint32_t* r, uint32_t addr) {
    asm volatile("ldmatrix.sync.aligned.m8n8.x2.shared.b16 {%0,%1}, [%2];"
        : "=r"(r[0]), "=r"(r[1]) : "r"(addr));
}
__device__ __forceinline__ void mma16816(float* d, const uint32_t* a, const uint32_t* b) {
    asm volatile("mma.sync.aligned.m16n8k16.row.col.f32.bf16.bf16.f32 "
        "{%0,%1,%2,%3}, {%4,%5,%6,%7}, {%8,%9}, {%0,%1,%2,%3};"
        : "+f"(d[0]), "+f"(d[1]), "+f"(d[2]), "+f"(d[3])
        : "r"(a[0]), "r"(a[1]), "r"(a[2]), "r"(a[3]), "r"(b[0]), "r"(b[1]));
}
__device__ __forceinline__ void cp16(uint32_t dst, const void* src) {
    asm volatile("cp.async.cg.shared.global [%0], [%1], 16;"
        :: "r"(dst), "l"(src));
}
#define CP_COMMIT() asm volatile("cp.async.commit_group;" ::: "memory")
#define CP_WAIT0()  asm volatile("cp.async.wait_group 0;" ::: "memory")

// 128B-row smem tile, XOR swizzle on 16B columns (conflict-free ldmatrix)
#define SWADDR(row, c16) ((uint32_t)((row) * 128 + (((c16) ^ ((row) & 7)) << 4)))

// ------- 1) fused: pad + bf16-split x  AND  per-channel mean --------------
// one block per (b, ci) channel
__global__ __launch_bounds__(256) void k_ctxpad(const float* __restrict__ x) {
    int pc = blockIdx.x;                     // b*CIN + ci
    const float* xc = x + (size_t)pc * HW;
    uint32_t* xp = g_xpad + (size_t)pc * HP * HP;
    float s = 0.f;
    for (int idx = threadIdx.x; idx < HP*HP; idx += 256) {
        int hp = idx / HP;
        int wp = idx - hp * HP;
        float v = 0.f;
        if (hp >= 1 && hp <= HH && wp >= 1 && wp <= WW) {
            v = xc[(hp - 1) * WW + (wp - 1)];
            s += v;
        }
        __nv_bfloat16 hi = __float2bfloat16(v);
        __nv_bfloat16 lo = __float2bfloat16(v - __bfloat162float(hi));
        __nv_bfloat16_raw hr = hi, lr = lo;
        xp[idx] = (uint32_t)hr.x | ((uint32_t)lr.x << 16);
    }
    __shared__ float sm[256];
    sm[threadIdx.x] = s; __syncthreads();
    #pragma unroll
    for (int off = 128; off > 0; off >>= 1) {
        if (threadIdx.x < off) sm[threadIdx.x] += sm[threadIdx.x + off];
        __syncthreads();
    }
    if (threadIdx.x == 0) g_ctx[pc] = sm[0] * (1.0f / HW);
}

// ---------------- 2) small attention heads ----------------
__global__ void k_attn(const float* __restrict__ fsw, const float* __restrict__ fsb,
                       const float* __restrict__ fiw, const float* __restrict__ fib,
                       const float* __restrict__ fow, const float* __restrict__ fob) {
    int gw   = (blockIdx.x * blockDim.x + threadIdx.x) >> 5;
    int lane = threadIdx.x & 31;
    const int NS = BB*KK, NI = BB*CIN, NO = BB*COUT;
    if (gw >= NS + NI + NO) return;
    int b; const float* wrow; float bias; float* dst;
    if (gw < NS) {
        b = gw / KK; int r = gw % KK;
        wrow = fsw + r*CIN; bias = fsb[r]; dst = &g_attn_sp[gw];
    } else if (gw < NS + NI) {
        int g = gw - NS; b = g / CIN; int r = g % CIN;
        wrow = fiw + r*CIN; bias = fib[r]; dst = &g_attn_in[g];
    } else {
        int g = gw - NS - NI; b = g / COUT; int r = g % COUT;
        wrow = fow + r*CIN; bias = fob[r]; dst = &g_attn_out[g];
    }
    const float* ctx = g_ctx + b*CIN;
    float s = 0.f;
    #pragma unroll
    for (int j = lane; j < CIN; j += 32) s += ctx[j] * wrow[j];
    #pragma unroll
    for (int o = 16; o > 0; o >>= 1) s += __shfl_down_sync(0xffffffffu, s, o);
    if (lane == 0) *dst = 1.f / (1.f + expf(-(s + bias)));
}

// ------- 3) big-GEMM + sigmoid + 5-way multiply, smem-staged weights ------
// block: 256 threads <-> 256 rows; K processed in 4 chunks of 32 floats,
// weight tile staged through smem via coalesced cp.async (double buffered).
#define CK     32
#define WROWB  144                 // bytes per smem row: 32 floats + 16B pad
#define DSTG   (256*WROWB)         // 36864 bytes per stage
#define DYN_SMEM (8192 + 2*DSTG)   // ctx (8KB) + 2 stages = 81920

__global__ __launch_bounds__(256) void k_dyn(const float* __restrict__ base_kernel,
                                             const float* __restrict__ fkw,
                                             const float* __restrict__ fkb) {
    extern __shared__ char dsm[];
    float* ctx_s = (float*)dsm;
    uint32_t sbase = smem_u32(dsm);
    int tid = threadIdx.x;
    for (int i = tid; i < BB*CIN; i += 256) ctx_s[i] = g_ctx[i];

    int r0 = blockIdx.x * 256;
    int r  = r0 + tid;

    auto loadW = [&](int c, uint32_t stg) {
        int k0 = c * CK;
        const float* src0 = fkw + (size_t)r0 * CIN + k0;
        #pragma unroll
        for (int cc = 0; cc < 8; cc++) {
            int i = cc * 256 + tid;       // 0..2047
            int row  = i >> 3;
            int col4 = i & 7;
            cp16(sbase + 8192 + stg + row * WROWB + col4 * 16,
                 src0 + (size_t)row * CIN + col4 * 4);
        }
    };

    float acc[BB];
    #pragma unroll
    for (int b = 0; b < BB; b++) acc[b] = 0.f;

    loadW(0, 0);
    CP_COMMIT();
    __syncthreads();   // ctx_s ready

    for (int c = 0; c < 4; c++) {
        uint32_t s_stg = (c & 1) ? DSTG : 0;
        uint32_t n_stg = (c & 1) ? 0 : DSTG;
        CP_WAIT0();
        __syncthreads();
        if (c < 3) { loadW(c + 1, n_stg); CP_COMMIT(); }

        const float4* wrow = (const float4*)(dsm + 8192 + s_stg + tid * WROWB);
        int k0 = c * CK;
        #pragma unroll
        for (int u = 0; u < 8; u++) {
            float4 w4 = wrow[u];
            #pragma unroll
            for (int b = 0; b < BB; b++) {
                const float* cb = ctx_s + b * CIN + k0 + u * 4;
                acc[b] += w4.x*cb[0] + w4.y*cb[1] + w4.z*cb[2] + w4.w*cb[3];
            }
        }
        __syncthreads();   // protect s_stg before it is reloaded
    }

    int o   = r / KDIM;
    int rem = r - o*KDIM;
    int i   = rem / KK;
    int kk  = rem - i*KK;
    float bk = base_kernel[r];
    float fb = fkb[r];
    #pragma unroll
    for (int b = 0; b < BB; b++) {
        float sg = 1.f / (1.f + expf(-(acc[b] + fb)));
        float v  = bk * g_attn_out[b*COUT + o] * g_attn_in[b*CIN + i]
                      * g_attn_sp[b*KK + kk] * sg;
        __nv_bfloat16 hi = __float2bfloat16(v);
        __nv_bfloat16 lo = __float2bfloat16(v - __bfloat162float(hi));
        size_t idx = (size_t)b * COUT * KDIM + r;
        g_dynA_hi[idx] = hi;
        g_dynA_lo[idx] = lo;
    }
}

// -------- 4) tensor-core conv via mma.sync bf16, double-buffered ----------
// Per stage: Ahi 8KB | Alo 8KB | Bhi 14KB | Blo 14KB = 44KB; 2 stages; 2 CTAs/SM.
#define OFF_AHI  0
#define OFF_ALO  8192
#define OFF_BHI  16384
#define OFF_BLO  30720
#define STG      45056
#define SMEM_BYTES (2*STG)   // 90112

__global__ __launch_bounds__(256, 2) void k_conv_mma(const float* __restrict__ bias,
                                                     float* __restrict__ out) {
    extern __shared__ char smem[];
    uint32_t sbase = smem_u32(smem);
    int tid  = threadIdx.x;
    int wid  = tid >> 5;
    int lane = tid & 31;

    int b  = blockIdx.z;
    int m0 = blockIdx.y * BM;
    int n0 = blockIdx.x * BN;

    const __nv_bfloat16* Ahi = g_dynA_hi + (size_t)(b*COUT + m0) * KDIM;
    const __nv_bfloat16* Alo = g_dynA_lo + (size_t)(b*COUT + m0) * KDIM;
    const uint32_t* Xp = g_xpad + (size_t)b * CIN * HP * HP;

    // warp tile: 16(m) x 56(n)
    int warp_m = (wid & 3) * 16;
    int warp_n = (wid >> 2) * 56;

    // per-lane ldmatrix addressing
    int amat  = lane >> 3;
    int arow0 = warp_m + (amat & 1) * 8 + (lane & 7);
    int ac16  = amat >> 1;
    int brow_l = (lane & 7);
    int bc16   = (lane >> 3) & 1;

    // B gather mapping: kc = tid>>2 (0..63), q = tid&3
    int kc = tid >> 2;
    int q  = tid & 3;
    int h_local = q >> 1;
    int w0 = (q & 1) * 28;
    int nbase = q * 28;
    int hbase = blockIdx.x * 2;
    int c16b = kc >> 3;
    int b2   = (kc & 7) * 2;

    float acc[7][4];
    #pragma unroll
    for (int nt = 0; nt < 7; nt++)
        #pragma unroll
        for (int i = 0; i < 4; i++) acc[nt][i] = 0.f;

    auto loadA = [&](int kt, uint32_t stg_off) {
        int k0 = kt * BK;
        #pragma unroll
        for (int c = 0; c < 2; c++) {
            int idx = c * 256 + tid;       // 0..511
            int row = idx >> 3;            // 0..63
            int c16 = idx & 7;
            size_t src = (size_t)row * KDIM + k0 + c16 * 8;
            uint32_t off = SWADDR(row, c16);
            cp16(sbase + stg_off + OFF_AHI + off, Ahi + src);
            cp16(sbase + stg_off + OFF_ALO + off, Alo + src);
        }
    };
    auto gatherLd = [&](int kt, uint32_t* pf) {
        int k  = kt * BK + kc;
        int ci = k / 9;
        int r9 = k - ci * 9;
        int kh = r9 / 3;
        int kw = r9 - kh * 3;
        const uint32_t* src = Xp + (size_t)(ci * HP + hbase + h_local + kh) * HP
                                 + (w0 + kw);
        #pragma unroll
        for (int j = 0; j < 28; j++) pf[j] = src[j];
    };
    auto gatherSt = [&](const uint32_t* pf, uint32_t stg_off) {
        #pragma unroll
        for (int j = 0; j < 28; j++) {
            uint32_t off = SWADDR(nbase + j, c16b) + b2;
            *(uint16_t*)(smem + stg_off + OFF_BHI + off) = (uint16_t)pf[j];
            *(uint16_t*)(smem + stg_off + OFF_BLO + off) = (uint16_t)(pf[j] >> 16);
        }
    };

    // ---- prologue: stage 0 = chunk 0 ----
    {
        uint32_t pf[28];
        loadA(0, 0);
        CP_COMMIT();
        gatherLd(0, pf);
        gatherSt(pf, 0);
    }

    for (int kt = 0; kt < NCHUNK; kt++) {
        uint32_t s_off = (kt & 1) ? STG : 0;
        uint32_t n_off = (kt & 1) ? 0 : STG;
        CP_WAIT0();
        __syncthreads();

        bool hn = (kt + 1) < NCHUNK;
        uint32_t pf[28];
        if (hn) {
            loadA(kt + 1, n_off);
            CP_COMMIT();
            gatherLd(kt + 1, pf);
        }

        // ---- compute: 4 k16-steps, 3 split-terms ----
        #pragma unroll
        for (int ks = 0; ks < 4; ks++) {
            uint32_t ahi[4], alo[4], bf[7][2];
            uint32_t aoff = SWADDR(arow0, ks*2 + ac16);
            ldm_x4(ahi, sbase + s_off + OFF_AHI + aoff);
            ldm_x4(alo, sbase + s_off + OFF_ALO + aoff);
            #pragma unroll
            for (int nt = 0; nt < 7; nt++) {
                uint32_t boff = SWADDR(warp_n + nt*8 + brow_l, ks*2 + bc16);
                ldm_x2(bf[nt], sbase + s_off + OFF_BHI + boff);
            }
            #pragma unroll
            for (int nt = 0; nt < 7; nt++) mma16816(acc[nt], ahi, bf[nt]);
            #pragma unroll
            for (int nt = 0; nt < 7; nt++) mma16816(acc[nt], alo, bf[nt]);
            #pragma unroll
            for (int nt = 0; nt < 7; nt++) {
                uint32_t boff = SWADDR(warp_n + nt*8 + brow_l, ks*2 + bc16);
                ldm_x2(bf[nt], sbase + s_off + OFF_BLO + boff);
            }
            #pragma unroll
            for (int nt = 0; nt < 7; nt++) mma16816(acc[nt], ahi, bf[nt]);
        }

        if (hn) gatherSt(pf, n_off);
    }

    // ---- epilogue: D frag -> gmem with bias ----
    int r4 = lane >> 2;
    int c2 = (lane & 3) * 2;
    int or0 = m0 + warp_m + r4;
    float bi0 = bias[or0];
    float bi1 = bias[or0 + 8];
    float* op0 = out + ((size_t)b * COUT + or0    ) * HW + n0 + warp_n + c2;
    float* op1 = out + ((size_t)b * COUT + or0 + 8) * HW + n0 + warp_n + c2;
    #pragma unroll
    for (int nt = 0; nt < 7; nt++) {
        float2 v0 = make_float2(acc[nt][0] + bi0, acc[nt][1] + bi0);
        float2 v1 = make_float2(acc[nt][2] + bi1, acc[nt][3] + bi1);
        *(float2*)(op0 + nt*8) = v0;
        *(float2*)(op1 + nt*8) = v1;
    }
}

// ---------------- launch ----------------
extern "C" void kernel_launch(void* const* d_in, const int* in_sizes, int n_in,
                              void* d_out, int out_size) {
    const float* x    = (const float*)d_in[0];
    const float* bk   = (const float*)d_in[1];
    const float* bias = (const float*)d_in[2];
    const float* fsw  = (const float*)d_in[3];
    const float* fsb  = (const float*)d_in[4];
    const float* fiw  = (const float*)d_in[5];
    const float* fib  = (const float*)d_in[6];
    const float* fow  = (const float*)d_in[7];
    const float* fob  = (const float*)d_in[8];
    const float* fkw  = (const float*)d_in[9];
    const float* fkb  = (const float*)d_in[10];
    float* out = (float*)d_out;

    k_ctxpad<<<BB*CIN, 256>>>(x);

    int total_warps = BB * (KK + CIN + COUT);
    k_attn<<<(total_warps*32 + 255)/256, 256>>>(fsw, fsb, fiw, fib, fow, fob);

    cudaFuncSetAttribute(k_dyn, cudaFuncAttributeMaxDynamicSharedMemorySize,
                         DYN_SMEM);
    k_dyn<<<(COUT*KDIM)/256, 256, DYN_SMEM>>>(bk, fkw, fkb);

    cudaFuncSetAttribute(k_conv_mma, cudaFuncAttributeMaxDynamicSharedMemorySize,
                         SMEM_BYTES);
    dim3 grid(HW/BN, COUT/BM, BB);   // (28, 4, 16)
    k_conv_mma<<<grid, 256, SMEM_BYTES>>>(bias, out);
}

// round 6
// speedup vs baseline: 1.7209x; 1.7209x over previous
#include <cuda_runtime.h>
#include <cuda_fp16.h>
#include <cstdint>
#include <math.h>

#define BB   16
#define CIN  128
#define COUT 256
#define KK   9
#define HH   56
#define WW   56
#define HW   3136
#define KDIM (CIN*KK)   // 1152
#define HP   58         // padded H/W

// GEMM tiling (mma.sync fp16 path)
#define BM 128
#define BN 112          // 3136 = 28 * 112 ; covers exactly 2 image rows
#define BK 64           // fp16 K per mainloop chunk (one 128B row)
#define NCHUNK (KDIM/BK) // 18

// ---------------- device scratch (no allocations allowed) ----------------
__device__ float g_ctx[BB*CIN];
__device__ float g_attn_sp[BB*KK];
__device__ float g_attn_in[BB*CIN];
__device__ float g_attn_out[BB*COUT];
__device__ __align__(16) __half g_dynA_hi[(size_t)BB*COUT*KDIM]; // 9.4MB
__device__ __align__(16) __half g_dynA_lo[(size_t)BB*COUT*KDIM]; // 9.4MB
__device__ __align__(16) uint16_t g_xpad[(size_t)BB*CIN*HP*HP];  // 13.8MB fp16

// ======================= helpers =====================
__device__ __forceinline__ uint32_t smem_u32(const void* p) {
    uint32_t a;
    asm("{ .reg .u64 t; cvta.to.shared.u64 t, %1; cvt.u32.u64 %0, t; }"
        : "=r"(a) : "l"(p));
    return a;
}
__device__ __forceinline__ void ldm_x4(uint32_t* r, uint32_t addr) {
    asm volatile("ldmatrix.sync.aligned.m8n8.x4.shared.b16 {%0,%1,%2,%3}, [%4];"
        : "=r"(r[0]), "=r"(r[1]), "=r"(r[2]), "=r"(r[3]) : "r"(addr));
}
__device__ __forceinline__ void ldm_x2(uint32_t* r, uint32_t addr) {
    asm volatile("ldmatrix.sync.aligned.m8n8.x2.shared.b16 {%0,%1}, [%2];"
        : "=r"(r[0]), "=r"(r[1]) : "r"(addr));
}
__device__ __forceinline__ void mma16816(float* d, const uint32_t* a, const uint32_t* b) {
    asm volatile("mma.sync.aligned.m16n8k16.row.col.f32.f16.f16.f32 "
        "{%0,%1,%2,%3}, {%4,%5,%6,%7}, {%8,%9}, {%0,%1,%2,%3};"
        : "+f"(d[0]), "+f"(d[1]), "+f"(d[2]), "+f"(d[3])
        : "r"(a[0]), "r"(a[1]), "r"(a[2]), "r"(a[3]), "r"(b[0]), "r"(b[1]));
}
__device__ __forceinline__ void cp16(uint32_t dst, const void* src) {
    asm volatile("cp.async.cg.shared.global [%0], [%1], 16;"
        :: "r"(dst), "l"(src));
}
#define CP_COMMIT() asm volatile("cp.async.commit_group;" ::: "memory")
#define CP_WAIT0()  asm volatile("cp.async.wait_group 0;" ::: "memory")

// 128B-row smem tile, XOR swizzle on 16B columns (conflict-free ldmatrix)
#define SWADDR(row, c16) ((uint32_t)((row) * 128 + (((c16) ^ ((row) & 7)) << 4)))

// ------- 1) fused: pad + fp16 x  AND  per-channel mean --------------------
__global__ __launch_bounds__(256) void k_ctxpad(const float* __restrict__ x) {
    int pc = blockIdx.x;                     // b*CIN + ci
    const float* xc = x + (size_t)pc * HW;
    uint16_t* xp = g_xpad + (size_t)pc * HP * HP;
    float s = 0.f;
    for (int idx = threadIdx.x; idx < HP*HP; idx += 256) {
        int hp = idx / HP;
        int wp = idx - hp * HP;
        float v = 0.f;
        if (hp >= 1 && hp <= HH && wp >= 1 && wp <= WW) {
            v = xc[(hp - 1) * WW + (wp - 1)];
            s += v;
        }
        __half_raw hr = __float2half_rn(v);
        xp[idx] = hr.x;
    }
    __shared__ float sm[256];
    sm[threadIdx.x] = s; __syncthreads();
    #pragma unroll
    for (int off = 128; off > 0; off >>= 1) {
        if (threadIdx.x < off) sm[threadIdx.x] += sm[threadIdx.x + off];
        __syncthreads();
    }
    if (threadIdx.x == 0) g_ctx[pc] = sm[0] * (1.0f / HW);
}

// ---------------- 2) small attention heads ----------------
__global__ void k_attn(const float* __restrict__ fsw, const float* __restrict__ fsb,
                       const float* __restrict__ fiw, const float* __restrict__ fib,
                       const float* __restrict__ fow, const float* __restrict__ fob) {
    int gw   = (blockIdx.x * blockDim.x + threadIdx.x) >> 5;
    int lane = threadIdx.x & 31;
    const int NS = BB*KK, NI = BB*CIN, NO = BB*COUT;
    if (gw >= NS + NI + NO) return;
    int b; const float* wrow; float bias; float* dst;
    if (gw < NS) {
        b = gw / KK; int r = gw % KK;
        wrow = fsw + r*CIN; bias = fsb[r]; dst = &g_attn_sp[gw];
    } else if (gw < NS + NI) {
        int g = gw - NS; b = g / CIN; int r = g % CIN;
        wrow = fiw + r*CIN; bias = fib[r]; dst = &g_attn_in[g];
    } else {
        int g = gw - NS - NI; b = g / COUT; int r = g % COUT;
        wrow = fow + r*CIN; bias = fob[r]; dst = &g_attn_out[g];
    }
    const float* ctx = g_ctx + b*CIN;
    float s = 0.f;
    #pragma unroll
    for (int j = lane; j < CIN; j += 32) s += ctx[j] * wrow[j];
    #pragma unroll
    for (int o = 16; o > 0; o >>= 1) s += __shfl_down_sync(0xffffffffu, s, o);
    if (lane == 0) *dst = 1.f / (1.f + expf(-(s + bias)));
}

// ------- 3) big-GEMM + sigmoid + 5-way multiply, smem-staged weights ------
#define CK     32
#define WROWB  144                 // bytes per smem row: 32 floats + 16B pad
#define DSTG   (256*WROWB)         // 36864 bytes per stage
#define DYN_SMEM (8192 + 2*DSTG)   // ctx (8KB) + 2 stages = 81920

__global__ __launch_bounds__(256) void k_dyn(const float* __restrict__ base_kernel,
                                             const float* __restrict__ fkw,
                                             const float* __restrict__ fkb) {
    extern __shared__ char dsm[];
    float* ctx_s = (float*)dsm;
    uint32_t sbase = smem_u32(dsm);
    int tid = threadIdx.x;
    for (int i = tid; i < BB*CIN; i += 256) ctx_s[i] = g_ctx[i];

    int r0 = blockIdx.x * 256;
    int r  = r0 + tid;

    auto loadW = [&](int c, uint32_t stg) {
        int k0 = c * CK;
        const float* src0 = fkw + (size_t)r0 * CIN + k0;
        #pragma unroll
        for (int cc = 0; cc < 8; cc++) {
            int i = cc * 256 + tid;
            int row  = i >> 3;
            int col4 = i & 7;
            cp16(sbase + 8192 + stg + row * WROWB + col4 * 16,
                 src0 + (size_t)row * CIN + col4 * 4);
        }
    };

    float acc[BB];
    #pragma unroll
    for (int b = 0; b < BB; b++) acc[b] = 0.f;

    loadW(0, 0);
    CP_COMMIT();
    __syncthreads();

    for (int c = 0; c < 4; c++) {
        uint32_t s_stg = (c & 1) ? DSTG : 0;
        uint32_t n_stg = (c & 1) ? 0 : DSTG;
        CP_WAIT0();
        __syncthreads();
        if (c < 3) { loadW(c + 1, n_stg); CP_COMMIT(); }

        const float4* wrow = (const float4*)(dsm + 8192 + s_stg + tid * WROWB);
        int k0 = c * CK;
        #pragma unroll
        for (int u = 0; u < 8; u++) {
            float4 w4 = wrow[u];
            #pragma unroll
            for (int b = 0; b < BB; b++) {
                const float* cb = ctx_s + b * CIN + k0 + u * 4;
                acc[b] += w4.x*cb[0] + w4.y*cb[1] + w4.z*cb[2] + w4.w*cb[3];
            }
        }
        __syncthreads();
    }

    int o   = r / KDIM;
    int rem = r - o*KDIM;
    int i   = rem / KK;
    int kk  = rem - i*KK;
    float bk = base_kernel[r];
    float fb = fkb[r];
    #pragma unroll
    for (int b = 0; b < BB; b++) {
        float sg = 1.f / (1.f + expf(-(acc[b] + fb)));
        float v  = bk * g_attn_out[b*COUT + o] * g_attn_in[b*CIN + i]
                      * g_attn_sp[b*KK + kk] * sg;
        __half hi = __float2half_rn(v);
        __half lo = __float2half_rn(v - __half2float(hi));
        size_t idx = (size_t)b * COUT * KDIM + r;
        g_dynA_hi[idx] = hi;
        g_dynA_lo[idx] = lo;
    }
}

// -------- 4) tensor-core conv via mma.sync fp16 (2-term A split) ----------
// Per stage: Ahi 16KB | Alo 16KB | B 14KB = 46KB; 2 stages; 2 CTAs/SM.
#define OFF_AHI  0
#define OFF_ALO  16384
#define OFF_B    32768
#define STG      47104
#define SMEM_BYTES (2*STG)   // 94208

__global__ __launch_bounds__(256, 2) void k_conv_mma(const float* __restrict__ bias,
                                                     float* __restrict__ out) {
    extern __shared__ char smem[];
    uint32_t sbase = smem_u32(smem);
    int tid  = threadIdx.x;
    int wid  = tid >> 5;
    int lane = tid & 31;

    int b  = blockIdx.z;
    int m0 = blockIdx.y * BM;
    int n0 = blockIdx.x * BN;

    const __half* Ahi = g_dynA_hi + (size_t)(b*COUT + m0) * KDIM;
    const __half* Alo = g_dynA_lo + (size_t)(b*COUT + m0) * KDIM;
    const uint16_t* Xp = g_xpad + (size_t)b * CIN * HP * HP;

    // warp tile: 32(m) x 56(n)
    int warp_m = (wid & 3) * 32;
    int warp_n = (wid >> 2) * 56;

    // per-lane ldmatrix addressing
    int amat  = lane >> 3;
    int arow0 = warp_m + (amat & 1) * 8 + (lane & 7);
    int ac16  = amat >> 1;
    int brow_l = (lane & 7);
    int bc16   = (lane >> 3) & 1;

    // B gather mapping: kc = tid>>2 (0..63), q = tid&3
    int kc = tid >> 2;
    int q  = tid & 3;
    int h_local = q >> 1;
    int w0 = (q & 1) * 28;
    int nbase = q * 28;
    int hbase = blockIdx.x * 2;
    int c16b = kc >> 3;
    int b2   = (kc & 7) * 2;

    float acc[2][7][4];
    #pragma unroll
    for (int t = 0; t < 2; t++)
        #pragma unroll
        for (int nt = 0; nt < 7; nt++)
            #pragma unroll
            for (int i = 0; i < 4; i++) acc[t][nt][i] = 0.f;

    auto loadA = [&](int kt, uint32_t stg_off) {
        int k0 = kt * BK;
        #pragma unroll
        for (int c = 0; c < 4; c++) {
            int idx = c * 256 + tid;       // 0..1023
            int row = idx >> 3;            // 0..127
            int c16 = idx & 7;
            size_t src = (size_t)row * KDIM + k0 + c16 * 8;
            uint32_t off = SWADDR(row, c16);
            cp16(sbase + stg_off + OFF_AHI + off, Ahi + src);
            cp16(sbase + stg_off + OFF_ALO + off, Alo + src);
        }
    };
    auto gatherB = [&](int kt, uint32_t stg_off) {
        int k  = kt * BK + kc;
        int ci = k / 9;
        int r9 = k - ci * 9;
        int kh = r9 / 3;
        int kw = r9 - kh * 3;
        const uint16_t* src = Xp + (size_t)(ci * HP + hbase + h_local + kh) * HP
                                 + (w0 + kw);
        #pragma unroll
        for (int j = 0; j < 28; j++) {
            uint16_t v = src[j];
            uint32_t off = SWADDR(nbase + j, c16b) + b2;
            *(uint16_t*)(smem + stg_off + OFF_B + off) = v;
        }
    };

    // ---- prologue: stage 0 = chunk 0 ----
    loadA(0, 0);
    CP_COMMIT();
    gatherB(0, 0);

    for (int kt = 0; kt < NCHUNK; kt++) {
        uint32_t s_off = (kt & 1) ? STG : 0;
        uint32_t n_off = (kt & 1) ? 0 : STG;
        CP_WAIT0();
        __syncthreads();

        if (kt + 1 < NCHUNK) {
            loadA(kt + 1, n_off);
            CP_COMMIT();
            gatherB(kt + 1, n_off);
        }

        // ---- compute: 4 k16-steps, 2 split-terms ----
        #pragma unroll
        for (int ks = 0; ks < 4; ks++) {
            uint32_t ahi[2][4], alo[2][4], bf[7][2];
            #pragma unroll
            for (int t = 0; t < 2; t++) {
                uint32_t aoff = SWADDR(arow0 + t*16, ks*2 + ac16);
                ldm_x4(ahi[t], sbase + s_off + OFF_AHI + aoff);
                ldm_x4(alo[t], sbase + s_off + OFF_ALO + aoff);
            }
            #pragma unroll
            for (int nt = 0; nt < 7; nt++) {
                uint32_t boff = SWADDR(warp_n + nt*8 + brow_l, ks*2 + bc16);
                ldm_x2(bf[nt], sbase + s_off + OFF_B + boff);
            }
            #pragma unroll
            for (int nt = 0; nt < 7; nt++)
                #pragma unroll
                for (int t = 0; t < 2; t++)
                    mma16816(acc[t][nt], ahi[t], bf[nt]);
            #pragma unroll
            for (int nt = 0; nt < 7; nt++)
                #pragma unroll
                for (int t = 0; t < 2; t++)
                    mma16816(acc[t][nt], alo[t], bf[nt]);
        }
    }

    // ---- epilogue: D frag -> gmem with bias ----
    int r4 = lane >> 2;
    int c2 = (lane & 3) * 2;
    #pragma unroll
    for (int t = 0; t < 2; t++) {
        int or0 = m0 + warp_m + t*16 + r4;
        float bi0 = bias[or0];
        float bi1 = bias[or0 + 8];
        float* op0 = out + ((size_t)b * COUT + or0    ) * HW + n0 + warp_n + c2;
        float* op1 = out + ((size_t)b * COUT + or0 + 8) * HW + n0 + warp_n + c2;
        #pragma unroll
        for (int nt = 0; nt < 7; nt++) {
            float2 v0 = make_float2(acc[t][nt][0] + bi0, acc[t][nt][1] + bi0);
            float2 v1 = make_float2(acc[t][nt][2] + bi1, acc[t][nt][3] + bi1);
            *(float2*)(op0 + nt*8) = v0;
            *(float2*)(op1 + nt*8) = v1;
        }
    }
}

// ---------------- launch ----------------
extern "C" void kernel_launch(void* const* d_in, const int* in_sizes, int n_in,
                              void* d_out, int out_size) {
    const float* x    = (const float*)d_in[0];
    const float* bk   = (const float*)d_in[1];
    const float* bias = (const float*)d_in[2];
    const float* fsw  = (const float*)d_in[3];
    const float* fsb  = (const float*)d_in[4];
    const float* fiw  = (const float*)d_in[5];
    const float* fib  = (const float*)d_in[6];
    const float* fow  = (const float*)d_in[7];
    const float* fob  = (const float*)d_in[8];
    const float* fkw  = (const float*)d_in[9];
    const float* fkb  = (const float*)d_in[10];
    float* out = (float*)d_out;

    k_ctxpad<<<BB*CIN, 256>>>(x);

    int total_warps = BB * (KK + CIN + COUT);
    k_attn<<<(total_warps*32 + 255)/256, 256>>>(fsw, fsb, fiw, fib, fow, fob);

    cudaFuncSetAttribute(k_dyn, cudaFuncAttributeMaxDynamicSharedMemorySize,
                         DYN_SMEM);
    k_dyn<<<(COUT*KDIM)/256, 256, DYN_SMEM>>>(bk, fkw, fkb);

    cudaFuncSetAttribute(k_conv_mma, cudaFuncAttributeMaxDynamicSharedMemorySize,
                         SMEM_BYTES);
    dim3 grid(HW/BN, COUT/BM, BB);   // (28, 2, 16)
    k_conv_mma<<<grid, 256, SMEM_BYTES>>>(bias, out);
}

// round 7
// speedup vs baseline: 2.0963x; 1.2181x over previous
#include <cuda_runtime.h>
#include <cuda_fp16.h>
#include <cstdint>
#include <math.h>

#define BB   16
#define CIN  128
#define COUT 256
#define KK   9
#define HH   56
#define WW   56
#define HW   3136
#define KDIM (CIN*KK)   // 1152
#define HP   58         // padded H/W

// GEMM tiling (mma.sync fp16 path)
#define BM 128
#define BN 112          // 3136 = 28 * 112 ; covers exactly 2 image rows
#define BK 64           // fp16 K per mainloop chunk (one 128B row)
#define NCHUNK (KDIM/BK) // 18

// ---------------- device scratch (no allocations allowed) ----------------
__device__ float g_ctx[BB*CIN];
__device__ float g_attn_sp[BB*KK];
__device__ float g_attn_in[BB*CIN];
__device__ float g_attn_out[BB*COUT];
__device__ __align__(16) __half g_dynA[(size_t)BB*COUT*KDIM];    // 9.4MB fp16
__device__ __align__(16) uint16_t g_xpad[(size_t)BB*CIN*HP*HP];  // 13.8MB fp16

// ======================= helpers =====================
__device__ __forceinline__ uint32_t smem_u32(const void* p) {
    uint32_t a;
    asm("{ .reg .u64 t; cvta.to.shared.u64 t, %1; cvt.u32.u64 %0, t; }"
        : "=r"(a) : "l"(p));
    return a;
}
__device__ __forceinline__ void ldm_x4(uint32_t* r0, uint32_t* r1, uint32_t* r2,
                                       uint32_t* r3, uint32_t addr) {
    asm volatile("ldmatrix.sync.aligned.m8n8.x4.shared.b16 {%0,%1,%2,%3}, [%4];"
        : "=r"(*r0), "=r"(*r1), "=r"(*r2), "=r"(*r3) : "r"(addr));
}
__device__ __forceinline__ void ldm_x2(uint32_t* r, uint32_t addr) {
    asm volatile("ldmatrix.sync.aligned.m8n8.x2.shared.b16 {%0,%1}, [%2];"
        : "=r"(r[0]), "=r"(r[1]) : "r"(addr));
}
__device__ __forceinline__ void mma16816(float* d, const uint32_t* a, const uint32_t* b) {
    asm volatile("mma.sync.aligned.m16n8k16.row.col.f32.f16.f16.f32 "
        "{%0,%1,%2,%3}, {%4,%5,%6,%7}, {%8,%9}, {%0,%1,%2,%3};"
        : "+f"(d[0]), "+f"(d[1]), "+f"(d[2]), "+f"(d[3])
        : "r"(a[0]), "r"(a[1]), "r"(a[2]), "r"(a[3]), "r"(b[0]), "r"(b[1]));
}
__device__ __forceinline__ void cp16(uint32_t dst, const void* src) {
    asm volatile("cp.async.cg.shared.global [%0], [%1], 16;"
        :: "r"(dst), "l"(src));
}
#define CP_COMMIT() asm volatile("cp.async.commit_group;" ::: "memory")
#define CP_WAIT0()  asm volatile("cp.async.wait_group 0;" ::: "memory")

// 128B-row smem tile, XOR swizzle on 16B columns (conflict-free ldmatrix)
#define SWADDR(row, c16) ((uint32_t)((row) * 128 + (((c16) ^ ((row) & 7)) << 4)))

// ------- 1) fused: pad + fp16 x  AND  per-channel mean --------------------
__global__ __launch_bounds__(256) void k_ctxpad(const float* __restrict__ x) {
    int pc = blockIdx.x;                     // b*CIN + ci
    const float* xc = x + (size_t)pc * HW;
    uint16_t* xp = g_xpad + (size_t)pc * HP * HP;
    float s = 0.f;
    for (int idx = threadIdx.x; idx < HP*HP; idx += 256) {
        int hp = idx / HP;
        int wp = idx - hp * HP;
        float v = 0.f;
        if (hp >= 1 && hp <= HH && wp >= 1 && wp <= WW) {
            v = xc[(hp - 1) * WW + (wp - 1)];
            s += v;
        }
        __half_raw hr = __float2half_rn(v);
        xp[idx] = hr.x;
    }
    __shared__ float sm[256];
    sm[threadIdx.x] = s; __syncthreads();
    #pragma unroll
    for (int off = 128; off > 0; off >>= 1) {
        if (threadIdx.x < off) sm[threadIdx.x] += sm[threadIdx.x + off];
        __syncthreads();
    }
    if (threadIdx.x == 0) g_ctx[pc] = sm[0] * (1.0f / HW);
}

// ---------------- 2) small attention heads ----------------
__global__ void k_attn(const float* __restrict__ fsw, const float* __restrict__ fsb,
                       const float* __restrict__ fiw, const float* __restrict__ fib,
                       const float* __restrict__ fow, const float* __restrict__ fob) {
    int gw   = (blockIdx.x * blockDim.x + threadIdx.x) >> 5;
    int lane = threadIdx.x & 31;
    const int NS = BB*KK, NI = BB*CIN, NO = BB*COUT;
    if (gw >= NS + NI + NO) return;
    int b; const float* wrow; float bias; float* dst;
    if (gw < NS) {
        b = gw / KK; int r = gw % KK;
        wrow = fsw + r*CIN; bias = fsb[r]; dst = &g_attn_sp[gw];
    } else if (gw < NS + NI) {
        int g = gw - NS; b = g / CIN; int r = g % CIN;
        wrow = fiw + r*CIN; bias = fib[r]; dst = &g_attn_in[g];
    } else {
        int g = gw - NS - NI; b = g / COUT; int r = g % COUT;
        wrow = fow + r*CIN; bias = fob[r]; dst = &g_attn_out[g];
    }
    const float* ctx = g_ctx + b*CIN;
    float s = 0.f;
    #pragma unroll
    for (int j = lane; j < CIN; j += 32) s += ctx[j] * wrow[j];
    #pragma unroll
    for (int o = 16; o > 0; o >>= 1) s += __shfl_down_sync(0xffffffffu, s, o);
    if (lane == 0) *dst = 1.f / (1.f + expf(-(s + bias)));
}

// ------- 3) big-GEMM + sigmoid + 5-way multiply, smem-staged weights ------
#define CK     32
#define WROWB  144                 // bytes per smem row: 32 floats + 16B pad
#define DSTG   (256*WROWB)         // 36864 bytes per stage
#define DYN_SMEM (8192 + 2*DSTG)   // ctx (8KB) + 2 stages = 81920

__global__ __launch_bounds__(256) void k_dyn(const float* __restrict__ base_kernel,
                                             const float* __restrict__ fkw,
                                             const float* __restrict__ fkb) {
    extern __shared__ char dsm[];
    float* ctx_s = (float*)dsm;
    uint32_t sbase = smem_u32(dsm);
    int tid = threadIdx.x;
    for (int i = tid; i < BB*CIN; i += 256) ctx_s[i] = g_ctx[i];

    int r0 = blockIdx.x * 256;
    int r  = r0 + tid;

    auto loadW = [&](int c, uint32_t stg) {
        int k0 = c * CK;
        const float* src0 = fkw + (size_t)r0 * CIN + k0;
        #pragma unroll
        for (int cc = 0; cc < 8; cc++) {
            int i = cc * 256 + tid;
            int row  = i >> 3;
            int col4 = i & 7;
            cp16(sbase + 8192 + stg + row * WROWB + col4 * 16,
                 src0 + (size_t)row * CIN + col4 * 4);
        }
    };

    float acc[BB];
    #pragma unroll
    for (int b = 0; b < BB; b++) acc[b] = 0.f;

    loadW(0, 0);
    CP_COMMIT();
    __syncthreads();

    for (int c = 0; c < 4; c++) {
        uint32_t s_stg = (c & 1) ? DSTG : 0;
        uint32_t n_stg = (c & 1) ? 0 : DSTG;
        CP_WAIT0();
        __syncthreads();
        if (c < 3) { loadW(c + 1, n_stg); CP_COMMIT(); }

        const float4* wrow = (const float4*)(dsm + 8192 + s_stg + tid * WROWB);
        int k0 = c * CK;
        #pragma unroll
        for (int u = 0; u < 8; u++) {
            float4 w4 = wrow[u];
            #pragma unroll
            for (int b = 0; b < BB; b++) {
                const float* cb = ctx_s + b * CIN + k0 + u * 4;
                acc[b] += w4.x*cb[0] + w4.y*cb[1] + w4.z*cb[2] + w4.w*cb[3];
            }
        }
        __syncthreads();
    }

    int o   = r / KDIM;
    int rem = r - o*KDIM;
    int i   = rem / KK;
    int kk  = rem - i*KK;
    float bk = base_kernel[r];
    float fb = fkb[r];
    #pragma unroll
    for (int b = 0; b < BB; b++) {
        float sg = 1.f / (1.f + expf(-(acc[b] + fb)));
        float v  = bk * g_attn_out[b*COUT + o] * g_attn_in[b*CIN + i]
                      * g_attn_sp[b*KK + kk] * sg;
        g_dynA[(size_t)b * COUT * KDIM + r] = __float2half_rn(v);
    }
}

// -------- 4) tensor-core conv via mma.sync fp16 (single pass) -------------
// Per stage: A 16KB | B 14KB = 30KB; 2 stages; 2 CTAs/SM.
#define OFF_A    0
#define OFF_B    16384
#define STG      30720
#define SMEM_BYTES (2*STG)   // 61440

__global__ __launch_bounds__(256, 2) void k_conv_mma(const float* __restrict__ bias,
                                                     float* __restrict__ out) {
    extern __shared__ char smem[];
    uint32_t sbase = smem_u32(smem);
    int tid  = threadIdx.x;
    int wid  = tid >> 5;
    int lane = tid & 31;

    int b  = blockIdx.z;
    int m0 = blockIdx.y * BM;
    int n0 = blockIdx.x * BN;

    const __half* A = g_dynA + (size_t)(b*COUT + m0) * KDIM;
    const uint16_t* Xp = g_xpad + (size_t)b * CIN * HP * HP;

    // warp tile: 32(m) x 56(n)
    int warp_m = (wid & 3) * 32;
    int warp_n = (wid >> 2) * 56;

    // per-lane ldmatrix addressing
    int amat  = lane >> 3;
    int arow0 = warp_m + (amat & 1) * 8 + (lane & 7);
    int ac16  = amat >> 1;
    // B x4 (pairs of nt): matrix sel -> nt within pair via lane bit4, k-half via bit3
    int browx4 = warp_n + ((lane >> 4) & 1) * 8 + (lane & 7);
    int bhalf  = (lane >> 3) & 1;
    // B x2 (last nt): lanes 0-15 supply addresses
    int brow_l = (lane & 7);
    int bc16   = (lane >> 3) & 1;

    // B gather mapping: kc = tid>>2 (0..63), q = tid&3
    int kc = tid >> 2;
    int q  = tid & 3;
    int h_local = q >> 1;
    int w0 = (q & 1) * 28;
    int nbase = q * 28;
    int hbase = blockIdx.x * 2;
    int c16b = kc >> 3;
    int b2   = (kc & 7) * 2;

    float acc[2][7][4];
    #pragma unroll
    for (int t = 0; t < 2; t++)
        #pragma unroll
        for (int nt = 0; nt < 7; nt++)
            #pragma unroll
            for (int i = 0; i < 4; i++) acc[t][nt][i] = 0.f;

    auto loadA = [&](int kt, uint32_t stg_off) {
        int k0 = kt * BK;
        #pragma unroll
        for (int c = 0; c < 4; c++) {
            int idx = c * 256 + tid;       // 0..1023
            int row = idx >> 3;            // 0..127
            int c16 = idx & 7;
            size_t src = (size_t)row * KDIM + k0 + c16 * 8;
            cp16(sbase + stg_off + OFF_A + SWADDR(row, c16), A + src);
        }
    };
    auto gatherB = [&](int kt, uint32_t stg_off) {
        int k  = kt * BK + kc;
        int ci = k / 9;
        int r9 = k - ci * 9;
        int kh = r9 / 3;
        int kw = r9 - kh * 3;
        const uint16_t* src = Xp + (size_t)(ci * HP + hbase + h_local + kh) * HP
                                 + (w0 + kw);
        #pragma unroll
        for (int j = 0; j < 28; j++) {
            uint16_t v = src[j];
            uint32_t off = SWADDR(nbase + j, c16b) + b2;
            *(uint16_t*)(smem + stg_off + OFF_B + off) = v;
        }
    };

    // ---- prologue: stage 0 = chunk 0 ----
    loadA(0, 0);
    CP_COMMIT();
    gatherB(0, 0);

    for (int kt = 0; kt < NCHUNK; kt++) {
        uint32_t s_off = (kt & 1) ? STG : 0;
        uint32_t n_off = (kt & 1) ? 0 : STG;
        CP_WAIT0();
        __syncthreads();

        if (kt + 1 < NCHUNK) {
            loadA(kt + 1, n_off);
            CP_COMMIT();
            gatherB(kt + 1, n_off);
        }

        // ---- compute: 4 k16-steps, single fp16 pass ----
        #pragma unroll
        for (int ks = 0; ks < 4; ks++) {
            uint32_t af[2][4], bf[7][2];
            #pragma unroll
            for (int t = 0; t < 2; t++) {
                uint32_t aoff = SWADDR(arow0 + t*16, ks*2 + ac16);
                ldm_x4(&af[t][0], &af[t][1], &af[t][2], &af[t][3],
                       sbase + s_off + OFF_A + aoff);
            }
            #pragma unroll
            for (int p = 0; p < 3; p++) {
                uint32_t boff = SWADDR(browx4 + p*16, ks*2 + bhalf);
                ldm_x4(&bf[2*p][0], &bf[2*p][1], &bf[2*p+1][0], &bf[2*p+1][1],
                       sbase + s_off + OFF_B + boff);
            }
            {
                uint32_t boff = SWADDR(warp_n + 48 + brow_l, ks*2 + bc16);
                ldm_x2(bf[6], sbase + s_off + OFF_B + boff);
            }
            #pragma unroll
            for (int nt = 0; nt < 7; nt++)
                #pragma unroll
                for (int t = 0; t < 2; t++)
                    mma16816(acc[t][nt], af[t], bf[nt]);
        }
    }

    // ---- epilogue: D frag -> gmem with bias ----
    int r4 = lane >> 2;
    int c2 = (lane & 3) * 2;
    #pragma unroll
    for (int t = 0; t < 2; t++) {
        int or0 = m0 + warp_m + t*16 + r4;
        float bi0 = bias[or0];
        float bi1 = bias[or0 + 8];
        float* op0 = out + ((size_t)b * COUT + or0    ) * HW + n0 + warp_n + c2;
        float* op1 = out + ((size_t)b * COUT + or0 + 8) * HW + n0 + warp_n + c2;
        #pragma unroll
        for (int nt = 0; nt < 7; nt++) {
            float2 v0 = make_float2(acc[t][nt][0] + bi0, acc[t][nt][1] + bi0);
            float2 v1 = make_float2(acc[t][nt][2] + bi1, acc[t][nt][3] + bi1);
            *(float2*)(op0 + nt*8) = v0;
            *(float2*)(op1 + nt*8) = v1;
        }
    }
}

// ---------------- launch ----------------
extern "C" void kernel_launch(void* const* d_in, const int* in_sizes, int n_in,
                              void* d_out, int out_size) {
    const float* x    = (const float*)d_in[0];
    const float* bk   = (const float*)d_in[1];
    const float* bias = (const float*)d_in[2];
    const float* fsw  = (const float*)d_in[3];
    const float* fsb  = (const float*)d_in[4];
    const float* fiw  = (const float*)d_in[5];
    const float* fib  = (const float*)d_in[6];
    const float* fow  = (const float*)d_in[7];
    const float* fob  = (const float*)d_in[8];
    const float* fkw  = (const float*)d_in[9];
    const float* fkb  = (const float*)d_in[10];
    float* out = (float*)d_out;

    k_ctxpad<<<BB*CIN, 256>>>(x);

    int total_warps = BB * (KK + CIN + COUT);
    k_attn<<<(total_warps*32 + 255)/256, 256>>>(fsw, fsb, fiw, fib, fow, fob);

    cudaFuncSetAttribute(k_dyn, cudaFuncAttributeMaxDynamicSharedMemorySize,
                         DYN_SMEM);
    k_dyn<<<(COUT*KDIM)/256, 256, DYN_SMEM>>>(bk, fkw, fkb);

    cudaFuncSetAttribute(k_conv_mma, cudaFuncAttributeMaxDynamicSharedMemorySize,
                         SMEM_BYTES);
    dim3 grid(HW/BN, COUT/BM, BB);   // (28, 2, 16)
    k_conv_mma<<<grid, 256, SMEM_BYTES>>>(bias, out);
}

// round 8
// speedup vs baseline: 2.3325x; 1.1127x over previous
#include <cuda_runtime.h>
#include <cuda_fp16.h>
#include <cstdint>
#include <math.h>

#define BB   16
#define CIN  128
#define COUT 256
#define KK   9
#define HH   56
#define WW   56
#define HW   3136
#define KDIM (CIN*KK)   // 1152
#define HP   58         // padded H
#define WP2  64         // padded/pair row stride (u32 units)

// GEMM tiling (mma.sync fp16 path)
#define BM 128
#define BN 112          // 3136 = 28 * 112 ; covers exactly 2 image rows
#define BK 64           // fp16 K per mainloop chunk
#define NCHUNK (KDIM/BK) // 18

// ---------------- device scratch (no allocations allowed) ----------------
__device__ float g_ctx[BB*CIN];
__device__ float g_attn_sp[BB*KK];
__device__ float g_attn_in[BB*CIN];
__device__ float g_attn_out[BB*COUT];
__device__ __align__(16) __half g_dynA[(size_t)BB*COUT*KDIM];    // 9.4MB fp16
// pair-duplicated padded image: P[pc][hp][w] = (x16(hp,w), x16(hp,w+1))
__device__ __align__(16) uint32_t g_xp2[(size_t)BB*CIN*HP*WP2];  // 30.4MB

// ======================= helpers =====================
__device__ __forceinline__ uint32_t smem_u32(const void* p) {
    uint32_t a;
    asm("{ .reg .u64 t; cvta.to.shared.u64 t, %1; cvt.u32.u64 %0, t; }"
        : "=r"(a) : "l"(p));
    return a;
}
__device__ __forceinline__ void ldm_x4(uint32_t* r0, uint32_t* r1, uint32_t* r2,
                                       uint32_t* r3, uint32_t addr) {
    asm volatile("ldmatrix.sync.aligned.m8n8.x4.shared.b16 {%0,%1,%2,%3}, [%4];"
        : "=r"(*r0), "=r"(*r1), "=r"(*r2), "=r"(*r3) : "r"(addr));
}
__device__ __forceinline__ void ldm_x4t(uint32_t* r0, uint32_t* r1, uint32_t* r2,
                                        uint32_t* r3, uint32_t addr) {
    asm volatile("ldmatrix.sync.aligned.m8n8.x4.trans.shared.b16 {%0,%1,%2,%3}, [%4];"
        : "=r"(*r0), "=r"(*r1), "=r"(*r2), "=r"(*r3) : "r"(addr));
}
__device__ __forceinline__ void ldm_x2t(uint32_t* r, uint32_t addr) {
    asm volatile("ldmatrix.sync.aligned.m8n8.x2.trans.shared.b16 {%0,%1}, [%2];"
        : "=r"(r[0]), "=r"(r[1]) : "r"(addr));
}
__device__ __forceinline__ void mma16816(float* d, const uint32_t* a, const uint32_t* b) {
    asm volatile("mma.sync.aligned.m16n8k16.row.col.f32.f16.f16.f32 "
        "{%0,%1,%2,%3}, {%4,%5,%6,%7}, {%8,%9}, {%0,%1,%2,%3};"
        : "+f"(d[0]), "+f"(d[1]), "+f"(d[2]), "+f"(d[3])
        : "r"(a[0]), "r"(a[1]), "r"(a[2]), "r"(a[3]), "r"(b[0]), "r"(b[1]));
}
__device__ __forceinline__ void cp16(uint32_t dst, const void* src) {
    asm volatile("cp.async.cg.shared.global [%0], [%1], 16;"
        :: "r"(dst), "l"(src));
}
#define CP_COMMIT() asm volatile("cp.async.commit_group;" ::: "memory")
#define CP_WAIT0()  asm volatile("cp.async.wait_group 0;" ::: "memory")

// 128B-row smem tile, XOR swizzle on 16B columns (A tile, non-trans ldmatrix)
#define SWADDR(row, c16) ((uint32_t)((row) * 128 + (((c16) ^ ((row) & 7)) << 4)))

// ------- 1) fused: pad + fp16-pair image AND per-channel mean -------------
__global__ __launch_bounds__(256) void k_ctxpad(const float* __restrict__ x) {
    int pc = blockIdx.x;                     // b*CIN + ci
    const float* xc = x + (size_t)pc * HW;
    uint32_t* xp = g_xp2 + (size_t)pc * HP * WP2;
    float s = 0.f;
    for (int idx = threadIdx.x; idx < HP*WP2; idx += 256) {
        int hp = idx >> 6;          // /WP2
        int w  = idx & 63;
        float v0 = 0.f, v1 = 0.f;
        if (hp >= 1 && hp <= HH) {
            const float* row = xc + (hp - 1) * WW;
            if (w >= 1 && w <= WW)     { v0 = row[w - 1]; s += v0; }
            if (w + 1 >= 1 && w + 1 <= WW) v1 = row[w];
        }
        __half_raw h0 = __float2half_rn(v0);
        __half_raw h1 = __float2half_rn(v1);
        xp[idx] = (uint32_t)h0.x | ((uint32_t)h1.x << 16);
    }
    __shared__ float sm[256];
    sm[threadIdx.x] = s; __syncthreads();
    #pragma unroll
    for (int off = 128; off > 0; off >>= 1) {
        if (threadIdx.x < off) sm[threadIdx.x] += sm[threadIdx.x + off];
        __syncthreads();
    }
    if (threadIdx.x == 0) g_ctx[pc] = sm[0] * (1.0f / HW);
}

// ---------------- 2) small attention heads ----------------
__global__ void k_attn(const float* __restrict__ fsw, const float* __restrict__ fsb,
                       const float* __restrict__ fiw, const float* __restrict__ fib,
                       const float* __restrict__ fow, const float* __restrict__ fob) {
    int gw   = (blockIdx.x * blockDim.x + threadIdx.x) >> 5;
    int lane = threadIdx.x & 31;
    const int NS = BB*KK, NI = BB*CIN, NO = BB*COUT;
    if (gw >= NS + NI + NO) return;
    int b; const float* wrow; float bias; float* dst;
    if (gw < NS) {
        b = gw / KK; int r = gw % KK;
        wrow = fsw + r*CIN; bias = fsb[r]; dst = &g_attn_sp[gw];
    } else if (gw < NS + NI) {
        int g = gw - NS; b = g / CIN; int r = g % CIN;
        wrow = fiw + r*CIN; bias = fib[r]; dst = &g_attn_in[g];
    } else {
        int g = gw - NS - NI; b = g / COUT; int r = g % COUT;
        wrow = fow + r*CIN; bias = fob[r]; dst = &g_attn_out[g];
    }
    const float* ctx = g_ctx + b*CIN;
    float s = 0.f;
    #pragma unroll
    for (int j = lane; j < CIN; j += 32) s += ctx[j] * wrow[j];
    #pragma unroll
    for (int o = 16; o > 0; o >>= 1) s += __shfl_down_sync(0xffffffffu, s, o);
    if (lane == 0) *dst = 1.f / (1.f + expf(-(s + bias)));
}

// ------- 3) big-GEMM + sigmoid + 5-way multiply, smem-staged weights ------
#define CK     32
#define WROWB  144                 // bytes per smem row: 32 floats + 16B pad
#define DSTG   (256*WROWB)         // 36864 bytes per stage
#define DYN_SMEM (8192 + 2*DSTG)   // ctx (8KB) + 2 stages = 81920

__global__ __launch_bounds__(256) void k_dyn(const float* __restrict__ base_kernel,
                                             const float* __restrict__ fkw,
                                             const float* __restrict__ fkb) {
    extern __shared__ char dsm[];
    float* ctx_s = (float*)dsm;
    uint32_t sbase = smem_u32(dsm);
    int tid = threadIdx.x;
    for (int i = tid; i < BB*CIN; i += 256) ctx_s[i] = g_ctx[i];

    int r0 = blockIdx.x * 256;
    int r  = r0 + tid;

    auto loadW = [&](int c, uint32_t stg) {
        int k0 = c * CK;
        const float* src0 = fkw + (size_t)r0 * CIN + k0;
        #pragma unroll
        for (int cc = 0; cc < 8; cc++) {
            int i = cc * 256 + tid;
            int row  = i >> 3;
            int col4 = i & 7;
            cp16(sbase + 8192 + stg + row * WROWB + col4 * 16,
                 src0 + (size_t)row * CIN + col4 * 4);
        }
    };

    float acc[BB];
    #pragma unroll
    for (int b = 0; b < BB; b++) acc[b] = 0.f;

    loadW(0, 0);
    CP_COMMIT();
    __syncthreads();

    for (int c = 0; c < 4; c++) {
        uint32_t s_stg = (c & 1) ? DSTG : 0;
        uint32_t n_stg = (c & 1) ? 0 : DSTG;
        CP_WAIT0();
        __syncthreads();
        if (c < 3) { loadW(c + 1, n_stg); CP_COMMIT(); }

        const float4* wrow = (const float4*)(dsm + 8192 + s_stg + tid * WROWB);
        int k0 = c * CK;
        #pragma unroll
        for (int u = 0; u < 8; u++) {
            float4 w4 = wrow[u];
            #pragma unroll
            for (int b = 0; b < BB; b++) {
                const float* cb = ctx_s + b * CIN + k0 + u * 4;
                acc[b] += w4.x*cb[0] + w4.y*cb[1] + w4.z*cb[2] + w4.w*cb[3];
            }
        }
        __syncthreads();
    }

    int o   = r / KDIM;
    int rem = r - o*KDIM;
    int i   = rem / KK;
    int kk  = rem - i*KK;
    float bk = base_kernel[r];
    float fb = fkb[r];
    #pragma unroll
    for (int b = 0; b < BB; b++) {
        float sg = 1.f / (1.f + expf(-(acc[b] + fb)));
        float v  = bk * g_attn_out[b*COUT + o] * g_attn_in[b*CIN + i]
                      * g_attn_sp[b*KK + kk] * sg;
        g_dynA[(size_t)b * COUT * KDIM + r] = __float2half_rn(v);
    }
}

// -------- 4) tensor-core conv via mma.sync fp16, K-major B ----------------
// Per stage: A 16KB (swizzled) | B 64x240B = 15360B; STG = 31744; 2 stages.
#define OFF_A    0
#define OFF_B    16384
#define BROWB    240
#define STG      31744
#define SMEM_BYTES (2*STG)   // 63488

__global__ __launch_bounds__(256, 2) void k_conv_mma(const float* __restrict__ bias,
                                                     float* __restrict__ out) {
    extern __shared__ char smem[];
    uint32_t sbase = smem_u32(smem);
    int tid  = threadIdx.x;
    int wid  = tid >> 5;
    int lane = tid & 31;

    int b  = blockIdx.z;
    int m0 = blockIdx.y * BM;
    int n0 = blockIdx.x * BN;

    const __half* A = g_dynA + (size_t)(b*COUT + m0) * KDIM;
    const uint32_t* Xp = g_xp2 + (size_t)b * CIN * HP * WP2;

    // warp tile: 32(m) x 56(n)
    int warp_m = (wid & 3) * 32;
    int warp_n = (wid >> 2) * 56;

    // per-lane A ldmatrix addressing (swizzled, non-trans)
    int amat  = lane >> 3;
    int arow0 = warp_m + (amat & 1) * 8 + (lane & 7);
    int ac16  = amat >> 1;
    // per-lane B trans-ldmatrix addressing ([k][n] K-major rows)
    int bg    = lane >> 3;                 // 0..3
    int bkrow = ((bg & 1) << 3) + (lane & 7);   // k within 16-step
    int bnx4  = warp_n + ((bg >> 1) << 3);      // + p*16 per pair
    int bkrow2 = (((lane >> 3) & 1) << 3) + (lane & 7);  // for x2

    // B gather mapping: kc = tid>>2 (0..63), q = tid&3
    int kc = tid >> 2;
    int q  = tid & 3;
    int h_local = q >> 1;          // image-row within 2-row band
    int j0 = (q & 1) * 28;         // n-offset within 56
    int hbase = blockIdx.x * 2;

    float acc[2][7][4];
    #pragma unroll
    for (int t = 0; t < 2; t++)
        #pragma unroll
        for (int nt = 0; nt < 7; nt++)
            #pragma unroll
            for (int i = 0; i < 4; i++) acc[t][nt][i] = 0.f;

    auto loadA = [&](int kt, uint32_t stg_off) {
        int k0 = kt * BK;
        #pragma unroll
        for (int c = 0; c < 4; c++) {
            int idx = c * 256 + tid;       // 0..1023
            int row = idx >> 3;            // 0..127
            int c16 = idx & 7;
            size_t src = (size_t)row * KDIM + k0 + c16 * 8;
            cp16(sbase + stg_off + OFF_A + SWADDR(row, c16), A + src);
        }
    };
    // load 14 consecutive-pair u32s for this thread's row quarter
    auto ldgB = [&](int kt, uint32_t* pf) {
        int k  = kt * BK + kc;
        int ci = k / 9;
        int r9 = k - ci * 9;
        int kh = r9 / 3;
        int kw = r9 - kh * 3;
        const uint32_t* src = Xp + (size_t)(ci * HP + hbase + h_local + kh) * WP2
                                 + (j0 + kw);
        #pragma unroll
        for (int p = 0; p < 14; p++) pf[p] = src[2*p];
    };
    auto stsB = [&](const uint32_t* pf, uint32_t stg_off) {
        // q -> n-quarter: n = (h_local*56 + j0) + 0..27 ; row = kc
        uint32_t dst = stg_off + OFF_B + kc * BROWB + (h_local * 56 + j0) * 2;
        #pragma unroll
        for (int p = 0; p < 7; p++)
            *(uint2*)(smem + dst + p * 8) = make_uint2(pf[2*p], pf[2*p+1]);
    };

    // ---- prologue: stage 0 = chunk 0 ----
    {
        uint32_t pf[14];
        loadA(0, 0);
        CP_COMMIT();
        ldgB(0, pf);
        stsB(pf, 0);
    }

    for (int kt = 0; kt < NCHUNK; kt++) {
        uint32_t s_off = (kt & 1) ? STG : 0;
        uint32_t n_off = (kt & 1) ? 0 : STG;
        CP_WAIT0();
        __syncthreads();

        bool hn = (kt + 1) < NCHUNK;
        uint32_t pf[14];
        if (hn) {
            loadA(kt + 1, n_off);
            CP_COMMIT();
            ldgB(kt + 1, pf);
        }

        // ---- compute: 4 k16-steps, single fp16 pass ----
        #pragma unroll
        for (int ks = 0; ks < 4; ks++) {
            uint32_t af[2][4], bf[7][2];
            #pragma unroll
            for (int t = 0; t < 2; t++) {
                uint32_t aoff = SWADDR(arow0 + t*16, ks*2 + ac16);
                ldm_x4(&af[t][0], &af[t][1], &af[t][2], &af[t][3],
                       sbase + s_off + OFF_A + aoff);
            }
            #pragma unroll
            for (int p = 0; p < 3; p++) {
                uint32_t boff = (uint32_t)((ks*16 + bkrow) * BROWB
                                           + (bnx4 + p*16) * 2);
                ldm_x4t(&bf[2*p][0], &bf[2*p][1], &bf[2*p+1][0], &bf[2*p+1][1],
                        sbase + s_off + OFF_B + boff);
            }
            {
                uint32_t boff = (uint32_t)((ks*16 + bkrow2) * BROWB
                                           + (warp_n + 48) * 2);
                ldm_x2t(bf[6], sbase + s_off + OFF_B + boff);
            }
            #pragma unroll
            for (int nt = 0; nt < 7; nt++)
                #pragma unroll
                for (int t = 0; t < 2; t++)
                    mma16816(acc[t][nt], af[t], bf[nt]);
        }

        if (hn) stsB(pf, n_off);
    }

    // ---- epilogue: D frag -> gmem with bias ----
    int r4 = lane >> 2;
    int c2 = (lane & 3) * 2;
    #pragma unroll
    for (int t = 0; t < 2; t++) {
        int or0 = m0 + warp_m + t*16 + r4;
        float bi0 = bias[or0];
        float bi1 = bias[or0 + 8];
        float* op0 = out + ((size_t)b * COUT + or0    ) * HW + n0 + warp_n + c2;
        float* op1 = out + ((size_t)b * COUT + or0 + 8) * HW + n0 + warp_n + c2;
        #pragma unroll
        for (int nt = 0; nt < 7; nt++) {
            float2 v0 = make_float2(acc[t][nt][0] + bi0, acc[t][nt][1] + bi0);
            float2 v1 = make_float2(acc[t][nt][2] + bi1, acc[t][nt][3] + bi1);
            *(float2*)(op0 + nt*8) = v0;
            *(float2*)(op1 + nt*8) = v1;
        }
    }
}

// ---------------- launch ----------------
extern "C" void kernel_launch(void* const* d_in, const int* in_sizes, int n_in,
                              void* d_out, int out_size) {
    const float* x    = (const float*)d_in[0];
    const float* bk   = (const float*)d_in[1];
    const float* bias = (const float*)d_in[2];
    const float* fsw  = (const float*)d_in[3];
    const float* fsb  = (const float*)d_in[4];
    const float* fiw  = (const float*)d_in[5];
    const float* fib  = (const float*)d_in[6];
    const float* fow  = (const float*)d_in[7];
    const float* fob  = (const float*)d_in[8];
    const float* fkw  = (const float*)d_in[9];
    const float* fkb  = (const float*)d_in[10];
    float* out = (float*)d_out;

    k_ctxpad<<<BB*CIN, 256>>>(x);

    int total_warps = BB * (KK + CIN + COUT);
    k_attn<<<(total_warps*32 + 255)/256, 256>>>(fsw, fsb, fiw, fib, fow, fob);

    cudaFuncSetAttribute(k_dyn, cudaFuncAttributeMaxDynamicSharedMemorySize,
                         DYN_SMEM);
    k_dyn<<<(COUT*KDIM)/256, 256, DYN_SMEM>>>(bk, fkw, fkb);

    cudaFuncSetAttribute(k_conv_mma, cudaFuncAttributeMaxDynamicSharedMemorySize,
                         SMEM_BYTES);
    dim3 grid(HW/BN, COUT/BM, BB);   // (28, 2, 16)
    k_conv_mma<<<grid, 256, SMEM_BYTES>>>(bias, out);
}